// round 12
// baseline (speedup 1.0000x reference)
#include <cuda_runtime.h>

// RITS recurrence v11 = v10 + initial-loader fix (+2*ll lane offset).
//  Software-pipelined 3-phase step; input-only work for t+1 computed at t.
//  P1: h@W_hist  | d(t+1)@W_gh        | hdec@U (reg cols)
//  P2: xc@W_feat | [gx;m](t+1)@W_beta | m(t+1)@Wm (reg cols)
//  P3: cc@Wcc (reg cols) + LSTM gates (lane-quad shfl gather)

#define TT 512
#define NIMP (256L * 3 * 512 * 64)
typedef unsigned long long ull;
typedef ulonglong2 ull2;

#define FMA2(acc, a, b) \
    asm("fma.rn.f32x2 %0, %1, %2, %0;" : "+l"(acc) : "l"(a), "l"(b))

__device__ __forceinline__ ull pk2(float x, float y) {
    ull r; asm("mov.b64 %0, {%1, %2};" : "=l"(r) : "f"(x), "f"(y)); return r;
}
__device__ __forceinline__ float fsum(ull v) {
    float2 r; asm("mov.b64 {%0, %1}, %2;" : "=f"(r.x), "=f"(r.y) : "l"(v));
    return r.x + r.y;
}
__device__ __forceinline__ float sigf(float x) { return 1.f / (1.f + __expf(-x)); }

// act chunk maps: 16-row chunks stride 20, 32-row chunks stride 36
#define CH20(k) (((k) >> 4) * 20 + ((k) & 15))
#define CH36(k) (((k) >> 5) * 36 + ((k) & 31))

__global__ __launch_bounds__(256, 1) void rits_kernel(
    const float* __restrict__ inputs,
    const float* __restrict__ W_hist, const float* __restrict__ b_hist,
    const float* __restrict__ W_feat, const float* __restrict__ b_feat,
    const float* __restrict__ W_gx,   const float* __restrict__ b_gx,
    const float* __restrict__ W_gh,   const float* __restrict__ b_gh,
    const float* __restrict__ W_beta, const float* __restrict__ b_beta,
    const float* __restrict__ W_lstm, const float* __restrict__ U_lstm,
    const float* __restrict__ b_lstm,
    const float* __restrict__ W_out,  const float* __restrict__ b_out,
    float* __restrict__ out)
{
    extern __shared__ __align__(16) float sm[];
    float* sWh_s  = sm;              // 4096  W_hist slab (w,iter,lane) float4
    float* sWgh_s = sWh_s  + 4096;   // 4096  W_gh slab
    float* sWf_s  = sWgh_s + 4096;   // 4096  W_feat_c slab
    float* sWb_s  = sWf_s  + 4096;   // 8192  W_beta slab
    float* sWgx   = sWb_s  + 8192;   // 64
    float* sbh    = sWgx + 64;
    float* sbf    = sbh  + 64;
    float* sbgx   = sbf  + 64;
    float* sbb    = sbgx + 64;
    float* sbgh   = sbb  + 64;
    float* hP     = sbgh + 64;       // 160  h, stride-20 chunks [s*80 + CH20]
    float* hdecS  = hP   + 160;      // 128  h*gamma_h [s*64+k] (broadcast)
    float* cS     = hdecS+ 128;      // 128
    float* xhat   = cS   + 128;      // 128  [s*64+j]
    float* xcP    = xhat + 128;      // 160  xc chunks [s*80 + CH20]
    float* gxm    = xcP  + 160;      // 288  [gx(t+1); m(t+1)] [s*144 + CH36(row)]
    float* ccS    = gxm  + 288;      // 128  [s*64+k] (broadcast)
    float* ghS    = ccS  + 128;      // 128  gamma_h(t+1) [s*64+j]
    float* inb    = ghS  + 128;      // 2*416: x[128] m[128] d chunks [s*80+CH20]

    const int tid  = threadIdx.x;
    const int bid  = blockIdx.x;
    const int lane = tid & 31;
    const int w    = tid >> 5;

    // ---- slabs: float4 of 4 consecutive rows for (j = w*8+(l>>2), kq = l&3) --
    for (int idx = tid; idx < 1024; idx += 256) {
        int ww = idx >> 7, rem = idx & 127, it = rem >> 5, l = rem & 31;
        int j = ww * 8 + (l >> 2), kqq = l & 3, row = kqq * 16 + 4 * it;
        ((float4*)sWh_s)[idx]  = make_float4(W_hist[row*64+j], W_hist[(row+1)*64+j],
                                             W_hist[(row+2)*64+j], W_hist[(row+3)*64+j]);
        ((float4*)sWgh_s)[idx] = make_float4(W_gh[row*64+j], W_gh[(row+1)*64+j],
                                             W_gh[(row+2)*64+j], W_gh[(row+3)*64+j]);
        float4 vf;
        vf.x = (row   == j) ? 0.f : W_feat[row*64+j];
        vf.y = (row+1 == j) ? 0.f : W_feat[(row+1)*64+j];
        vf.z = (row+2 == j) ? 0.f : W_feat[(row+2)*64+j];
        vf.w = (row+3 == j) ? 0.f : W_feat[(row+3)*64+j];
        ((float4*)sWf_s)[idx] = vf;
    }
    for (int idx = tid; idx < 2048; idx += 256) {
        int ww = idx >> 8, rem = idx & 255, it = rem >> 5, l = rem & 31;
        int j = ww * 8 + (l >> 2), kqq = l & 3, row = kqq * 32 + 4 * it;
        ((float4*)sWb_s)[idx] = make_float4(W_beta[row*64+j], W_beta[(row+1)*64+j],
                                            W_beta[(row+2)*64+j], W_beta[(row+3)*64+j]);
    }
    if (tid < 64) {
        sWgx[tid] = W_gx[tid * 64 + tid];
        sbh[tid]  = b_hist[tid];
        sbf[tid]  = b_feat[tid];
        sbgx[tid] = b_gx[tid];
        sbb[tid]  = b_beta[tid];
        sbgh[tid] = b_gh[tid];
    }
    if (tid < 160) hP[tid] = 0.f;
    if (tid < 128) { hdecS[tid] = 0.f; cS[tid] = 0.f; }

    // ---- thread decomposition (shared by all phases) ----
    const int jT = w * 8 + (lane >> 2);      // column j
    const int kq = lane & 3;                 // k-quarter (P1/P2) AND gate (P3)
    const int sE = kq;                       // epilogue sample (valid kq<2)
    const int colP = kq * 64 + jT;           // P3 fused column (gate*64 + j)

    // ---- register weights for column colP ----
    ull U2[32], Wm2[32], Wcc2[32];
#pragma unroll
    for (int q = 0; q < 32; q++) {
        U2[q]   = pk2(U_lstm[(2*q)*256 + colP],      U_lstm[(2*q+1)*256 + colP]);
        Wm2[q]  = pk2(W_lstm[(64+2*q)*256 + colP],   W_lstm[(65+2*q)*256 + colP]);
        Wcc2[q] = pk2(W_lstm[(2*q)*256 + colP],      W_lstm[(2*q+1)*256 + colP]);
    }
    const float blC = b_lstm[colP];

    // ---- input loader mapping (threads 0..191) ----
    const int ls = tid / 96;
    const int lr = tid % 96;
    const int lc = lr / 32;                  // 0=x 1=m 2=d
    const int ll = lr % 32;
    const long lbase = ((long)(2 * bid + ls) * 3 + lc) * TT * 64;
    const int loff = (lc < 2) ? lc * 128 + ls * 64 + 2 * ll
                              : 256 + ls * 80 + CH20(2 * ll);

    if (tid < 192) {                          // inputs(0) -> buf0, inputs(1) -> buf1
        *(float2*)&inb[loff]       = *(const float2*)&inputs[lbase + 2 * ll];
        *(float2*)&inb[416 + loff] = *(const float2*)&inputs[lbase + 64 + 2 * ll];
    }

    // output base pointers (epilogue owners kq<2, s=sE)
    float* outx = out + (((long)(2 * bid + sE) * 3 + 0) * TT) * 64 + jT;
    float* outz = out + (((long)(2 * bid + sE) * 3 + 1) * TT) * 64 + jT;
    float* outc = out + (((long)(2 * bid + sE) * 3 + 2) * TT) * 64 + jT;

    __syncthreads();

    // ================= PROLOGUE: gx(0)/m(0), bp(0), zM(0) =================
    if (tid < 128) {
        int s = tid >> 6, j = tid & 63;
        float d0 = inb[256 + s * 80 + CH20(j)];
        gxm[s * 144 + CH36(j)]      = __expf(-fmaxf(d0 * sWgx[j] + sbgx[j], 0.f));
        gxm[s * 144 + CH36(64 + j)] = inb[128 + s * 64 + j];
    }
    __syncthreads();

    float bpcS;            // beta-pre(t) for my (sE, jT)
    ull zMc0, zMc1;        // m(t)@Wm partial sums (packed)
    {
        ull b40 = 0, b41 = 0, m60 = 0, m61 = 0;
#pragma unroll
        for (int i = 0; i < 8; i++) {
            ull2 a0 = *(const ull2*)&gxm[kq * 36 + 4 * i];
            ull2 a1 = *(const ull2*)&gxm[144 + kq * 36 + 4 * i];
            ull2 wv = *(const ull2*)&sWb_s[((w * 8 + i) * 32 + lane) * 4];
            FMA2(b40, wv.x, a0.x); FMA2(b40, wv.y, a0.y);
            FMA2(b41, wv.x, a1.x); FMA2(b41, wv.y, a1.y);
        }
#pragma unroll
        for (int i = 0; i < 16; i++) {
            ull2 m0 = *(const ull2*)&inb[128 + 4 * i];
            ull2 m1 = *(const ull2*)&inb[128 + 64 + 4 * i];
            FMA2(m60, Wm2[2*i], m0.x); FMA2(m60, Wm2[2*i+1], m0.y);
            FMA2(m61, Wm2[2*i], m1.x); FMA2(m61, Wm2[2*i+1], m1.y);
        }
        float v0 = fsum(b40), v1 = fsum(b41);
#pragma unroll
        for (int off = 1; off <= 2; off <<= 1) {
            v0 += __shfl_xor_sync(0xffffffffu, v0, off);
            v1 += __shfl_xor_sync(0xffffffffu, v1, off);
        }
        bpcS = (kq == 1 ? v1 : v0) + sbb[jT];
        zMc0 = m60; zMc1 = m61;
    }
    __syncthreads();

    // ========================== MAIN LOOP ==========================
    int p = 0;
    for (int t = 0; t < TT; t++) {
        float* bufA = inb + p * 416;           // inputs(t)
        float* bufB = inb + (p ^ 1) * 416;     // inputs(t+1)

        float2 pf = make_float2(0.f, 0.f);
        if (tid < 192 && t + 2 < TT)
            pf = *(const float2*)&inputs[lbase + (long)(t + 2) * 64 + 2 * ll];

        ull zU0, zU1;                          // hdec@U for colP (this step)

        // ===== P1: h@W_hist | d(t+1)@W_gh | hdec@U =====
        {
            ull a10 = 0, a11 = 0, a30 = 0, a31 = 0, u0 = 0, u1 = 0;
            const float* dB = bufB + 256;
#pragma unroll
            for (int i = 0; i < 4; i++) {
                ull2 h0 = *(const ull2*)&hP[kq * 20 + 4 * i];
                ull2 h1 = *(const ull2*)&hP[80 + kq * 20 + 4 * i];
                ull2 wh = *(const ull2*)&sWh_s[((w * 4 + i) * 32 + lane) * 4];
                FMA2(a10, wh.x, h0.x); FMA2(a10, wh.y, h0.y);
                FMA2(a11, wh.x, h1.x); FMA2(a11, wh.y, h1.y);
                ull2 d0 = *(const ull2*)&dB[kq * 20 + 4 * i];
                ull2 d1 = *(const ull2*)&dB[80 + kq * 20 + 4 * i];
                ull2 wg = *(const ull2*)&sWgh_s[((w * 4 + i) * 32 + lane) * 4];
                FMA2(a30, wg.x, d0.x); FMA2(a30, wg.y, d0.y);
                FMA2(a31, wg.x, d1.x); FMA2(a31, wg.y, d1.y);
            }
#pragma unroll
            for (int i = 0; i < 16; i++) {
                ull2 hd0 = *(const ull2*)&hdecS[4 * i];
                ull2 hd1 = *(const ull2*)&hdecS[64 + 4 * i];
                FMA2(u0, U2[2*i], hd0.x); FMA2(u0, U2[2*i+1], hd0.y);
                FMA2(u1, U2[2*i], hd1.x); FMA2(u1, U2[2*i+1], hd1.y);
            }
            zU0 = u0; zU1 = u1;
            float x0 = fsum(a10), x1 = fsum(a11);
            float g0 = fsum(a30), g1 = fsum(a31);
#pragma unroll
            for (int off = 1; off <= 2; off <<= 1) {
                x0 += __shfl_xor_sync(0xffffffffu, x0, off);
                x1 += __shfl_xor_sync(0xffffffffu, x1, off);
                g0 += __shfl_xor_sync(0xffffffffu, g0, off);
                g1 += __shfl_xor_sync(0xffffffffu, g1, off);
            }
            if (kq < 2) {
                int s = sE, j = jT;
                float xh = (s ? x1 : x0) + sbh[j];
                xhat[s * 64 + j] = xh;
                float x = bufA[s * 64 + j], m = bufA[128 + s * 64 + j];
                xcP[s * 80 + CH20(j)] = m * x + (1.f - m) * xh;
                outx[(long)t * 64] = xh;
                ghS[s * 64 + j] = __expf(-fmaxf((s ? g1 : g0) + sbgh[j], 0.f));
                float dn = bufB[256 + s * 80 + CH20(j)];
                gxm[s * 144 + CH36(j)] =
                    __expf(-fmaxf(dn * sWgx[j] + sbgx[j], 0.f));
                gxm[s * 144 + CH36(64 + j)] = bufB[128 + s * 64 + j];
            }
        }
        __syncthreads();

        // ===== P2: xc@W_feat | [gx;m](t+1)@W_beta | m(t+1)@Wm =====
        ull zMn0 = 0, zMn1 = 0;
        {
            ull z50 = 0, z51 = 0, b40 = 0, b41 = 0;
#pragma unroll
            for (int i = 0; i < 4; i++) {
                ull2 a0 = *(const ull2*)&xcP[kq * 20 + 4 * i];
                ull2 a1 = *(const ull2*)&xcP[80 + kq * 20 + 4 * i];
                ull2 wv = *(const ull2*)&sWf_s[((w * 4 + i) * 32 + lane) * 4];
                FMA2(z50, wv.x, a0.x); FMA2(z50, wv.y, a0.y);
                FMA2(z51, wv.x, a1.x); FMA2(z51, wv.y, a1.y);
            }
#pragma unroll
            for (int i = 0; i < 8; i++) {
                ull2 a0 = *(const ull2*)&gxm[kq * 36 + 4 * i];
                ull2 a1 = *(const ull2*)&gxm[144 + kq * 36 + 4 * i];
                ull2 wv = *(const ull2*)&sWb_s[((w * 8 + i) * 32 + lane) * 4];
                FMA2(b40, wv.x, a0.x); FMA2(b40, wv.y, a0.y);
                FMA2(b41, wv.x, a1.x); FMA2(b41, wv.y, a1.y);
            }
#pragma unroll
            for (int i = 0; i < 16; i++) {
                ull2 m0 = *(const ull2*)&bufB[128 + 4 * i];
                ull2 m1 = *(const ull2*)&bufB[128 + 64 + 4 * i];
                FMA2(zMn0, Wm2[2*i], m0.x); FMA2(zMn0, Wm2[2*i+1], m0.y);
                FMA2(zMn1, Wm2[2*i], m1.x); FMA2(zMn1, Wm2[2*i+1], m1.y);
            }
            float z0 = fsum(z50), z1 = fsum(z51);
            float v0 = fsum(b40), v1 = fsum(b41);
#pragma unroll
            for (int off = 1; off <= 2; off <<= 1) {
                z0 += __shfl_xor_sync(0xffffffffu, z0, off);
                z1 += __shfl_xor_sync(0xffffffffu, z1, off);
                v0 += __shfl_xor_sync(0xffffffffu, v0, off);
                v1 += __shfl_xor_sync(0xffffffffu, v1, off);
            }
            if (kq < 2) {
                int s = sE, j = jT;
                float zh = (s ? z1 : z0) + sbf[j];
                float be = sigf(bpcS);                     // beta-pre(t), carried
                float ch = be * zh + (1.f - be) * xhat[s * 64 + j];
                float x = bufA[s * 64 + j], m = bufA[128 + s * 64 + j];
                ccS[s * 64 + j] = m * x + (1.f - m) * ch;
                outz[(long)t * 64] = zh;
                outc[(long)t * 64] = ch;
            }
            bpcS = (kq == 1 ? v1 : v0) + sbb[jT];          // beta-pre(t+1)
        }
        __syncthreads();

        // ===== P3: cc@Wcc + gates =====
        {
            ull c0 = 0, c1 = 0;
#pragma unroll
            for (int i = 0; i < 16; i++) {
                ull2 a0 = *(const ull2*)&ccS[4 * i];
                ull2 a1 = *(const ull2*)&ccS[64 + 4 * i];
                FMA2(c0, Wcc2[2*i], a0.x); FMA2(c0, Wcc2[2*i+1], a0.y);
                FMA2(c1, Wcc2[2*i], a1.x); FMA2(c1, Wcc2[2*i+1], a1.y);
            }
            float z0 = fsum(c0) + fsum(zU0) + fsum(zMc0) + blC;
            float z1 = fsum(c1) + fsum(zU1) + fsum(zMc1) + blC;
            float f0 = __shfl_xor_sync(0xffffffffu, z0, 1);
            float f1 = __shfl_xor_sync(0xffffffffu, z1, 1);
            float g0 = __shfl_xor_sync(0xffffffffu, z0, 2);
            float g1 = __shfl_xor_sync(0xffffffffu, z1, 2);
            float o0 = __shfl_xor_sync(0xffffffffu, z0, 3);
            float o1 = __shfl_xor_sync(0xffffffffu, z1, 3);
            if (kq == 0) {
                int j = jT;
                float cn0 = sigf(f0) * cS[j]      + sigf(z0) * tanhf(g0);
                float cn1 = sigf(f1) * cS[64 + j] + sigf(z1) * tanhf(g1);
                cS[j]      = cn0;
                cS[64 + j] = cn1;
                float hn0 = sigf(o0) * tanhf(cn0);
                float hn1 = sigf(o1) * tanhf(cn1);
                hP[CH20(j)]      = hn0;
                hP[80 + CH20(j)] = hn1;
                hdecS[j]      = hn0 * ghS[j];
                hdecS[64 + j] = hn1 * ghS[64 + j];
            }
        }
        zMc0 = zMn0; zMc1 = zMn1;                          // zM(t+1) for next step
        if (tid < 192 && t + 2 < TT)
            *(float2*)&inb[p * 416 + loff] = pf;           // inputs(t+2)
        p ^= 1;
        __syncthreads();
    }

    // ===== predictions: sigmoid(h_last @ W_out + b_out) =====
    if (tid < 64) {
        int s = tid >> 5, l = tid & 31;
        float v = hP[s * 80 + CH20(l)] * W_out[l]
                + hP[s * 80 + CH20(l + 32)] * W_out[l + 32];
#pragma unroll
        for (int off = 16; off; off >>= 1)
            v += __shfl_down_sync(0xffffffffu, v, off);
        if (l == 0)
            out[NIMP + 2 * bid + s] = 1.f / (1.f + __expf(-(v + b_out[0])));
    }
}

extern "C" void kernel_launch(void* const* d_in, const int* in_sizes, int n_in,
                              void* d_out, int out_size)
{
    const float* inputs = (const float*)d_in[0];
    const float* W_hist = (const float*)d_in[1];
    const float* b_hist = (const float*)d_in[2];
    const float* W_feat = (const float*)d_in[3];
    const float* b_feat = (const float*)d_in[4];
    const float* W_gx   = (const float*)d_in[5];
    const float* b_gx   = (const float*)d_in[6];
    const float* W_gh   = (const float*)d_in[7];
    const float* b_gh   = (const float*)d_in[8];
    const float* W_beta = (const float*)d_in[9];
    const float* b_beta = (const float*)d_in[10];
    const float* W_lstm = (const float*)d_in[11];
    const float* U_lstm = (const float*)d_in[12];
    const float* b_lstm = (const float*)d_in[13];
    const float* W_out  = (const float*)d_in[14];
    const float* b_out  = (const float*)d_in[15];

    const int smem_bytes = 23000 * (int)sizeof(float);   // 92,000 B
    cudaFuncSetAttribute(rits_kernel,
                         cudaFuncAttributeMaxDynamicSharedMemorySize, smem_bytes);

    rits_kernel<<<128, 256, smem_bytes>>>(
        inputs, W_hist, b_hist, W_feat, b_feat, W_gx, b_gx, W_gh, b_gh,
        W_beta, b_beta, W_lstm, U_lstm, b_lstm, W_out, b_out,
        (float*)d_out);
}